// round 3
// baseline (speedup 1.0000x reference)
#include <cuda_runtime.h>
#include <math.h>

// Problem constants
#define BATCH   64
#define SEQ     256
#define EMBD    256
#define UNITS   1024
#define N3      3072   // 3*UNITS

// ---------------------------------------------------------------------------
// Device scratch (static allocation only, per harness rules)
// ---------------------------------------------------------------------------
// gx[dir][t][b][3072]  (backward direction stored pre-reversed: index t holds
// token SEQ-1-t, so step kernels always read slab t)
__device__ float g_gx[2][(size_t)SEQ * BATCH * N3];     // 402 MB
// ping-pong hidden state [dir][parity][b][1024]
__device__ float g_h[2][2][BATCH * UNITS];

// ---------------------------------------------------------------------------
// Helpers
// ---------------------------------------------------------------------------
__device__ __forceinline__ float tf32r(float x) {
    unsigned u;
    asm("cvt.rna.tf32.f32 %0, %1;" : "=r"(u) : "f"(x));
    return __uint_as_float(u);
}

__device__ __forceinline__ void mma_tf32(float& c0, float& c1, float& c2, float& c3,
                                         unsigned a0, unsigned a1, unsigned a2, unsigned a3,
                                         unsigned b0, unsigned b1) {
    asm volatile(
        "mma.sync.aligned.m16n8k8.row.col.f32.tf32.tf32.f32 "
        "{%0,%1,%2,%3}, {%4,%5,%6,%7}, {%8,%9}, {%0,%1,%2,%3};\n"
        : "+f"(c0), "+f"(c1), "+f"(c2), "+f"(c3)
        : "r"(a0), "r"(a1), "r"(a2), "r"(a3), "r"(b0), "r"(b1));
}

__device__ __forceinline__ float sigmoidf_(float v) {
    return 1.0f / (1.0f + expf(-v));
}

// ---------------------------------------------------------------------------
// init: copy h0 into both direction buffers (parity 0)
// ---------------------------------------------------------------------------
__global__ void init_h(const float* __restrict__ hidden) {
    int i = blockIdx.x * blockDim.x + threadIdx.x;
    if (i < BATCH * UNITS) {
        float v = hidden[i];
        g_h[0][0][i] = v;
        g_h[1][0][i] = v;
    }
}

// ---------------------------------------------------------------------------
// gx kernel: gx[dir][t][b][n] = emb[tok(b,t,dir)] @ W + b_in
// Tile: M=64 (one timestep, all batches), N=64, K=256 (kc=32, 8 chunks)
// grid (256, 48, 2), block 128 (4 warps, each 16 rows x 64 cols)
// ---------------------------------------------------------------------------
__global__ __launch_bounds__(128) void gx_kernel(
    const int*   __restrict__ x,
    const float* __restrict__ emb,
    const float* __restrict__ Wf, const float* __restrict__ bf_in,
    const float* __restrict__ Wb, const float* __restrict__ bb_in)
{
    const int mt  = blockIdx.x;            // == timestep index t (step-kernel view)
    const int n0  = blockIdx.y * 64;
    const int dir = blockIdx.z;
    const float* W    = dir ? Wb : Wf;
    const float* bias = dir ? bb_in : bf_in;
    const int t_tok = dir ? (SEQ - 1 - mt) : mt;

    __shared__ float As[64][36];   // [row=b][k], pad 36 -> conflict-free frags
    __shared__ float Bs[32][72];   // [k][col],  pad 72
    __shared__ int   toks[64];

    const int tid = threadIdx.x;
    if (tid < 64) toks[tid] = x[tid * SEQ + t_tok];
    __syncthreads();

    const int warp = tid >> 5, lane = tid & 31;
    const int g = lane >> 2, tg = lane & 3;
    const int bb = warp * 16;

    float c[8][4];
    #pragma unroll
    for (int i = 0; i < 8; i++)
        #pragma unroll
        for (int e = 0; e < 4; e++) c[i][e] = 0.0f;

    // A load pattern: i<16: row b = 4i + (tid>>5), k = tid&31  (coalesced 128B)
    const int a_b4 = tid >> 5;
    const int a_k  = tid & 31;
    int arow[16];
    #pragma unroll
    for (int i = 0; i < 16; i++) arow[i] = toks[4 * i + a_b4] * EMBD + a_k;

    // B load pattern: i<16: k = 2i + (tid>>6), c = tid&63     (coalesced 256B)
    const int b_k2 = tid >> 6;
    const int b_c  = tid & 63;

    float a_reg[16], b_reg[16];
    #pragma unroll
    for (int i = 0; i < 16; i++) a_reg[i] = emb[arow[i]];
    #pragma unroll
    for (int i = 0; i < 16; i++) b_reg[i] = W[(2 * i + b_k2) * N3 + n0 + b_c];

    for (int kk = 0; kk < 8; kk++) {
        #pragma unroll
        for (int i = 0; i < 16; i++) As[4 * i + a_b4][a_k] = tf32r(a_reg[i]);
        #pragma unroll
        for (int i = 0; i < 16; i++) Bs[2 * i + b_k2][b_c] = tf32r(b_reg[i]);
        __syncthreads();

        if (kk < 7) {
            const int k0 = (kk + 1) * 32;
            #pragma unroll
            for (int i = 0; i < 16; i++) a_reg[i] = emb[arow[i] + k0];
            #pragma unroll
            for (int i = 0; i < 16; i++)
                b_reg[i] = W[(k0 + 2 * i + b_k2) * N3 + n0 + b_c];
        }

        #pragma unroll
        for (int ks = 0; ks < 4; ks++) {
            unsigned a0 = __float_as_uint(As[bb + g    ][ks * 8 + tg    ]);
            unsigned a1 = __float_as_uint(As[bb + g + 8][ks * 8 + tg    ]);
            unsigned a2 = __float_as_uint(As[bb + g    ][ks * 8 + tg + 4]);
            unsigned a3 = __float_as_uint(As[bb + g + 8][ks * 8 + tg + 4]);
            #pragma unroll
            for (int nt = 0; nt < 8; nt++) {
                unsigned b0 = __float_as_uint(Bs[ks * 8 + tg    ][nt * 8 + g]);
                unsigned b1 = __float_as_uint(Bs[ks * 8 + tg + 4][nt * 8 + g]);
                mma_tf32(c[nt][0], c[nt][1], c[nt][2], c[nt][3],
                         a0, a1, a2, a3, b0, b1);
            }
        }
        __syncthreads();
    }

    // epilogue: add bias, store [t][b][3072]
    float* gxo = &g_gx[dir][(size_t)mt * (BATCH * N3)];
    #pragma unroll
    for (int nt = 0; nt < 8; nt++) {
        const int col = n0 + nt * 8 + tg * 2;
        float2 bi = *(const float2*)(bias + col);
        float2 v0 = make_float2(c[nt][0] + bi.x, c[nt][1] + bi.y);
        float2 v1 = make_float2(c[nt][2] + bi.x, c[nt][3] + bi.y);
        *(float2*)(gxo + (size_t)(bb + g    ) * N3 + col) = v0;
        *(float2*)(gxo + (size_t)(bb + g + 8) * N3 + col) = v1;
    }
}

// ---------------------------------------------------------------------------
// step kernel: one GRU timestep, both directions.
// grid 128: cta = dir*64 + slice (16 units per slice)
// Per CTA: gr-cols = {z,r,h} x 16 units = 48, M=64 batches, K=1024 (kc=64).
// block 128 (4 warps x 16 rows x 48 cols).
// ---------------------------------------------------------------------------
__global__ __launch_bounds__(128, 1) void step_kernel(
    int t,
    const int*   __restrict__ x,
    const float* __restrict__ Uf, const float* __restrict__ bf_rec,
    const float* __restrict__ Ub, const float* __restrict__ bb_rec,
    float*       __restrict__ out)
{
    const int cta   = blockIdx.x;
    const int dir   = cta >> 6;
    const int slice = cta & 63;
    const int j0    = slice * 16;
    const float* U    = dir ? Ub : Uf;
    const float* brec = dir ? bb_rec : bf_rec;
    const int parity = t & 1;
    const float* h_in  = g_h[dir][parity];
    float*       h_out = g_h[dir][parity ^ 1];
    const int t_tok = dir ? (SEQ - 1 - t) : t;
    const float* gx = &g_gx[dir][(size_t)t * (BATCH * N3)];

    __shared__ float As[64][68];   // [row=b][k  0..63], pad 68
    __shared__ float Us[64][56];   // [k][col 0..47],   pad 56

    const int tid = threadIdx.x;
    const int warp = tid >> 5, lane = tid & 31;
    const int g = lane >> 2, tg = lane & 3;
    const int bb = warp * 16;

    float c[6][4];
    #pragma unroll
    for (int i = 0; i < 6; i++)
        #pragma unroll
        for (int e = 0; e < 4; e++) c[i][e] = 0.0f;

    // A loads: i<32: b = 2i + (tid>>6), k = tid&63   (coalesced 128B/warp)
    const int a_b = tid >> 6;
    const int a_k = tid & 63;
    // B loads: per gate g3, i<8: k = 8i + (tid>>4), c16 = tid&15 (64B groups)
    const int b_ko = tid >> 4;
    const int b_c  = tid & 15;

    float a_reg[32], b_reg[24];
    #pragma unroll
    for (int i = 0; i < 32; i++) a_reg[i] = h_in[(2 * i + a_b) * UNITS + a_k];
    #pragma unroll
    for (int g3 = 0; g3 < 3; g3++)
        #pragma unroll
        for (int i = 0; i < 8; i++)
            b_reg[g3 * 8 + i] = U[(8 * i + b_ko) * N3 + g3 * UNITS + j0 + b_c];

    for (int kk = 0; kk < 16; kk++) {
        #pragma unroll
        for (int i = 0; i < 32; i++) As[2 * i + a_b][a_k] = tf32r(a_reg[i]);
        #pragma unroll
        for (int g3 = 0; g3 < 3; g3++)
            #pragma unroll
            for (int i = 0; i < 8; i++)
                Us[8 * i + b_ko][g3 * 16 + b_c] = tf32r(b_reg[g3 * 8 + i]);
        __syncthreads();

        if (kk < 15) {
            const int k0 = (kk + 1) * 64;
            #pragma unroll
            for (int i = 0; i < 32; i++)
                a_reg[i] = h_in[(2 * i + a_b) * UNITS + k0 + a_k];
            #pragma unroll
            for (int g3 = 0; g3 < 3; g3++)
                #pragma unroll
                for (int i = 0; i < 8; i++)
                    b_reg[g3 * 8 + i] =
                        U[(k0 + 8 * i + b_ko) * N3 + g3 * UNITS + j0 + b_c];
        }

        #pragma unroll
        for (int ks = 0; ks < 8; ks++) {
            unsigned a0 = __float_as_uint(As[bb + g    ][ks * 8 + tg    ]);
            unsigned a1 = __float_as_uint(As[bb + g + 8][ks * 8 + tg    ]);
            unsigned a2 = __float_as_uint(As[bb + g    ][ks * 8 + tg + 4]);
            unsigned a3 = __float_as_uint(As[bb + g + 8][ks * 8 + tg + 4]);
            #pragma unroll
            for (int nt = 0; nt < 6; nt++) {
                unsigned b0 = __float_as_uint(Us[ks * 8 + tg    ][nt * 8 + g]);
                unsigned b1 = __float_as_uint(Us[ks * 8 + tg + 4][nt * 8 + g]);
                mma_tf32(c[nt][0], c[nt][1], c[nt][2], c[nt][3],
                         a0, a1, a2, a3, b0, b1);
            }
        }
        __syncthreads();
    }

    // ------------------- fused GRU gate epilogue -------------------
    // tiles 0,1 -> z ; 2,3 -> r ; 4,5 -> h. Same thread holds matching
    // (row, unit) positions across the three gates -> no shuffles.
    const bool m0 = (x[(bb + g    ) * SEQ + t_tok] != 0);
    const bool m1 = (x[(bb + g + 8) * SEQ + t_tok] != 0);

    #pragma unroll
    for (int ut = 0; ut < 2; ut++) {
        const int u = j0 + ut * 8 + tg * 2;
        float2 brz = *(const float2*)(brec + u);
        float2 brr = *(const float2*)(brec + UNITS + u);
        float2 brh = *(const float2*)(brec + 2 * UNITS + u);
        #pragma unroll
        for (int rr = 0; rr < 2; rr++) {
            const int b = bb + g + rr * 8;
            const bool m = rr ? m1 : m0;
            const float* gxr = gx + (size_t)b * N3;
            float2 xz = *(const float2*)(gxr + u);
            float2 xr = *(const float2*)(gxr + UNITS + u);
            float2 xh = *(const float2*)(gxr + 2 * UNITS + u);
            float2 ho = *(const float2*)(h_in + b * UNITS + u);

            float hn[2];
            #pragma unroll
            for (int cc = 0; cc < 2; cc++) {
                float cz = c[0 + ut][rr * 2 + cc];
                float cr = c[2 + ut][rr * 2 + cc];
                float ch = c[4 + ut][rr * 2 + cc];
                float xzv = cc ? xz.y : xz.x;
                float xrv = cc ? xr.y : xr.x;
                float xhv = cc ? xh.y : xh.x;
                float bz  = cc ? brz.y : brz.x;
                float br  = cc ? brr.y : brr.x;
                float bh  = cc ? brh.y : brh.x;
                float hov = cc ? ho.y : ho.x;

                float z  = sigmoidf_(xzv + cz + bz);
                float r  = sigmoidf_(xrv + cr + br);
                float hh = tanhf(xhv + r * (ch + bh));
                float v  = z * hov + (1.0f - z) * hh;
                hn[cc] = m ? v : hov;
            }
            *(float2*)(h_out + b * UNITS + u) = make_float2(hn[0], hn[1]);
            *(float2*)(out + (size_t)b * (SEQ * 2 * UNITS)
                           + (size_t)t_tok * (2 * UNITS)
                           + dir * UNITS + u) = make_float2(hn[0], hn[1]);
        }
    }
}

// ---------------------------------------------------------------------------
// projection: state = tanh([hf, hb] @ Wp + bp)   [64,2048]@[2048,1024]
// grid 64 (16-col tiles), block 256: jc = tid&15, 16 batch-groups of 4
// ---------------------------------------------------------------------------
__global__ __launch_bounds__(256) void proj_kernel(
    const float* __restrict__ Wp, const float* __restrict__ bp,
    float* __restrict__ out_state)
{
    const int j  = blockIdx.x * 16 + (threadIdx.x & 15);
    const int b0 = (threadIdx.x >> 4) * 4;
    const float* hf = g_h[0][0];
    const float* hb = g_h[1][0];

    float acc[4] = {0.f, 0.f, 0.f, 0.f};
    #pragma unroll 4
    for (int k = 0; k < UNITS; k++) {
        float w = Wp[k * UNITS + j];
        #pragma unroll
        for (int i = 0; i < 4; i++) acc[i] += hf[(b0 + i) * UNITS + k] * w;
    }
    #pragma unroll 4
    for (int k = 0; k < UNITS; k++) {
        float w = Wp[(UNITS + k) * UNITS + j];
        #pragma unroll
        for (int i = 0; i < 4; i++) acc[i] += hb[(b0 + i) * UNITS + k] * w;
    }
    float bj = bp[j];
    #pragma unroll
    for (int i = 0; i < 4; i++)
        out_state[(b0 + i) * UNITS + j] = tanhf(acc[i] + bj);
}

// ---------------------------------------------------------------------------
// launcher
// ---------------------------------------------------------------------------
extern "C" void kernel_launch(void* const* d_in, const int* in_sizes, int n_in,
                              void* d_out, int out_size)
{
    const int*   x      = (const int*)  d_in[0];
    const float* hidden = (const float*)d_in[1];
    const float* emb    = (const float*)d_in[2];
    const float* Wf     = (const float*)d_in[3];
    const float* Uf     = (const float*)d_in[4];
    const float* bf_in  = (const float*)d_in[5];
    const float* bf_rec = (const float*)d_in[6];
    const float* Wb     = (const float*)d_in[7];
    const float* Ub     = (const float*)d_in[8];
    const float* bb_in  = (const float*)d_in[9];
    const float* bb_rec = (const float*)d_in[10];
    const float* Wp     = (const float*)d_in[11];
    const float* bp     = (const float*)d_in[12];
    float* out = (float*)d_out;

    (void)in_sizes; (void)n_in; (void)out_size;

    init_h<<<(BATCH * UNITS + 255) / 256, 256>>>(hidden);

    gx_kernel<<<dim3(SEQ, N3 / 64, 2), 128>>>(x, emb, Wf, bf_in, Wb, bb_in);

    for (int t = 0; t < SEQ; t++)
        step_kernel<<<128, 128>>>(t, x, Uf, bf_rec, Ub, bb_rec, out);

    proj_kernel<<<UNITS / 16, 256>>>(Wp, bp,
                                     out + (size_t)BATCH * SEQ * 2 * UNITS);
}

// round 4
// speedup vs baseline: 1.3326x; 1.3326x over previous
#include <cuda_runtime.h>
#include <math.h>

// Problem constants
#define BATCH   64
#define SEQ     256
#define EMBD    256
#define UNITS   1024
#define N3      3072   // 3*UNITS

// ---------------------------------------------------------------------------
// Device scratch (static allocation only, per harness rules)
// ---------------------------------------------------------------------------
// gx[dir][t][b][3072]  (backward direction stored pre-reversed: index t holds
// token SEQ-1-t, so the recurrence always reads slab t)
__device__ float g_gx[2][(size_t)SEQ * BATCH * N3];     // 402 MB
// ping-pong hidden state [dir][parity][b][1024]
__device__ float g_h[2][2][BATCH * UNITS];
// U packed in mma-fragment order: [dir][slice64][k8 128][nt 6][lane 32][2]
// (tf32-converted). 2*64*128*384 floats = 25 MB.
__device__ float g_Upk[2][64][128 * 6 * 32 * 2];
// per-direction step counters for the persistent-kernel barrier
__device__ int g_cnt[2];

// ---------------------------------------------------------------------------
// Helpers
// ---------------------------------------------------------------------------
__device__ __forceinline__ float tf32r(float x) {
    unsigned u;
    asm("cvt.rna.tf32.f32 %0, %1;" : "=r"(u) : "f"(x));
    return __uint_as_float(u);
}

__device__ __forceinline__ void mma_tf32(float& c0, float& c1, float& c2, float& c3,
                                         unsigned a0, unsigned a1, unsigned a2, unsigned a3,
                                         unsigned b0, unsigned b1) {
    asm volatile(
        "mma.sync.aligned.m16n8k8.row.col.f32.tf32.tf32.f32 "
        "{%0,%1,%2,%3}, {%4,%5,%6,%7}, {%8,%9}, {%0,%1,%2,%3};\n"
        : "+f"(c0), "+f"(c1), "+f"(c2), "+f"(c3)
        : "r"(a0), "r"(a1), "r"(a2), "r"(a3), "r"(b0), "r"(b1));
}

__device__ __forceinline__ float sigmoidf_(float v) {
    return 1.0f / (1.0f + expf(-v));
}

// ---------------------------------------------------------------------------
// init: copy h0 into both direction buffers (parity 0) + reset step counters
// ---------------------------------------------------------------------------
__global__ void init_h(const float* __restrict__ hidden) {
    int i = blockIdx.x * blockDim.x + threadIdx.x;
    if (i < BATCH * UNITS) {
        float v = hidden[i];
        g_h[0][0][i] = v;
        g_h[1][0][i] = v;
    }
    if (i < 2) g_cnt[i] = 0;
}

// ---------------------------------------------------------------------------
// pack U into fragment order so the recurrence reads single LDS.64 per frag.
// One block per (k8, slice, dir); 384 threads -> (nt, lane, half).
//   b0 (half=0): U[k8*8+tg][col],  b1 (half=1): U[k8*8+tg+4][col]
//   col = gate*1024 + slice*16 + within,  col48 = nt*8+g
// ---------------------------------------------------------------------------
__global__ __launch_bounds__(384) void pack_U(
    const float* __restrict__ Uf, const float* __restrict__ Ub)
{
    const int k8    = blockIdx.x;
    const int slice = blockIdx.y;
    const int dir   = blockIdx.z;
    const float* U = dir ? Ub : Uf;

    const int tid  = threadIdx.x;
    const int half = tid & 1;
    const int lane = (tid >> 1) & 31;
    const int nt   = tid >> 6;
    const int g    = lane >> 2, tg = lane & 3;
    const int k    = k8 * 8 + tg + half * 4;
    const int col48 = nt * 8 + g;
    const int gate  = col48 >> 4;
    const int within = col48 & 15;

    float v = U[(size_t)k * N3 + gate * UNITS + slice * 16 + within];
    g_Upk[dir][slice][k8 * 384 + tid] = tf32r(v);
}

// ---------------------------------------------------------------------------
// gx kernel: gx[dir][t][b][n] = emb[tok(b,t,dir)] @ W + b_in
// Tile: M=64 (one timestep, all batches), N=64, K=256 (kc=32, 8 chunks)
// grid (256, 48, 2), block 128 (4 warps, each 16 rows x 64 cols)
// ---------------------------------------------------------------------------
__global__ __launch_bounds__(128) void gx_kernel(
    const int*   __restrict__ x,
    const float* __restrict__ emb,
    const float* __restrict__ Wf, const float* __restrict__ bf_in,
    const float* __restrict__ Wb, const float* __restrict__ bb_in)
{
    const int mt  = blockIdx.x;            // == timestep index t (recurrence view)
    const int n0  = blockIdx.y * 64;
    const int dir = blockIdx.z;
    const float* W    = dir ? Wb : Wf;
    const float* bias = dir ? bb_in : bf_in;
    const int t_tok = dir ? (SEQ - 1 - mt) : mt;

    __shared__ float As[64][36];
    __shared__ float Bs[32][72];
    __shared__ int   toks[64];

    const int tid = threadIdx.x;
    if (tid < 64) toks[tid] = x[tid * SEQ + t_tok];
    __syncthreads();

    const int warp = tid >> 5, lane = tid & 31;
    const int g = lane >> 2, tg = lane & 3;
    const int bb = warp * 16;

    float c[8][4];
    #pragma unroll
    for (int i = 0; i < 8; i++)
        #pragma unroll
        for (int e = 0; e < 4; e++) c[i][e] = 0.0f;

    const int a_b4 = tid >> 5;
    const int a_k  = tid & 31;
    int arow[16];
    #pragma unroll
    for (int i = 0; i < 16; i++) arow[i] = toks[4 * i + a_b4] * EMBD + a_k;

    const int b_k2 = tid >> 6;
    const int b_c  = tid & 63;

    float a_reg[16], b_reg[16];
    #pragma unroll
    for (int i = 0; i < 16; i++) a_reg[i] = emb[arow[i]];
    #pragma unroll
    for (int i = 0; i < 16; i++) b_reg[i] = W[(2 * i + b_k2) * N3 + n0 + b_c];

    for (int kk = 0; kk < 8; kk++) {
        #pragma unroll
        for (int i = 0; i < 16; i++) As[4 * i + a_b4][a_k] = tf32r(a_reg[i]);
        #pragma unroll
        for (int i = 0; i < 16; i++) Bs[2 * i + b_k2][b_c] = tf32r(b_reg[i]);
        __syncthreads();

        if (kk < 7) {
            const int k0 = (kk + 1) * 32;
            #pragma unroll
            for (int i = 0; i < 16; i++) a_reg[i] = emb[arow[i] + k0];
            #pragma unroll
            for (int i = 0; i < 16; i++)
                b_reg[i] = W[(k0 + 2 * i + b_k2) * N3 + n0 + b_c];
        }

        #pragma unroll
        for (int ks = 0; ks < 4; ks++) {
            unsigned a0 = __float_as_uint(As[bb + g    ][ks * 8 + tg    ]);
            unsigned a1 = __float_as_uint(As[bb + g + 8][ks * 8 + tg    ]);
            unsigned a2 = __float_as_uint(As[bb + g    ][ks * 8 + tg + 4]);
            unsigned a3 = __float_as_uint(As[bb + g + 8][ks * 8 + tg + 4]);
            #pragma unroll
            for (int nt = 0; nt < 8; nt++) {
                unsigned b0 = __float_as_uint(Bs[ks * 8 + tg    ][nt * 8 + g]);
                unsigned b1 = __float_as_uint(Bs[ks * 8 + tg + 4][nt * 8 + g]);
                mma_tf32(c[nt][0], c[nt][1], c[nt][2], c[nt][3],
                         a0, a1, a2, a3, b0, b1);
            }
        }
        __syncthreads();
    }

    float* gxo = &g_gx[dir][(size_t)mt * (BATCH * N3)];
    #pragma unroll
    for (int nt = 0; nt < 8; nt++) {
        const int col = n0 + nt * 8 + tg * 2;
        float2 bi = *(const float2*)(bias + col);
        float2 v0 = make_float2(c[nt][0] + bi.x, c[nt][1] + bi.y);
        float2 v1 = make_float2(c[nt][2] + bi.x, c[nt][3] + bi.y);
        *(float2*)(gxo + (size_t)(bb + g    ) * N3 + col) = v0;
        *(float2*)(gxo + (size_t)(bb + g + 8) * N3 + col) = v1;
    }
}

// ---------------------------------------------------------------------------
// Persistent recurrence kernel: all 256 timesteps, both directions.
// grid 128 (1 CTA/SM, all co-resident): cta = dir*64 + slice (16 units).
// Per CTA: U slice (1024 x 48) lives in SMEM in fragment order for the whole
// kernel. Per step: stage h chunk (64x64) -> SMEM, 48 MMAs/chunk, fused GRU
// epilogue, then release-counter barrier per direction.
// Dynamic SMEM: 192KB (U) + 17KB (A staging) = 214016 B.
// ---------------------------------------------------------------------------
#define SMEM_U_FLOATS (128 * 6 * 32 * 2)      // 49152
#define SMEM_TOTAL_B  ((SMEM_U_FLOATS + 64 * 68) * 4)

__global__ __launch_bounds__(128, 1) void recur_kernel(
    const int*   __restrict__ x,
    const float* __restrict__ bf_rec,
    const float* __restrict__ bb_rec,
    float*       __restrict__ out)
{
    extern __shared__ float smem[];
    float* Up = smem;                       // [k8][nt][lane][2]
    float (*As)[68] = (float (*)[68])(smem + SMEM_U_FLOATS);

    const int cta   = blockIdx.x;
    const int dir   = cta >> 6;
    const int slice = cta & 63;
    const int j0    = slice * 16;
    const float* brec = dir ? bb_rec : bf_rec;

    const int tid  = threadIdx.x;
    const int warp = tid >> 5, lane = tid & 31;
    const int g = lane >> 2, tg = lane & 3;
    const int bb = warp * 16;

    // ---- load U slice into SMEM once (192 KB, coalesced float4) ----
    {
        const float4* src = (const float4*)g_Upk[dir][slice];
        float4* dst = (float4*)Up;
        #pragma unroll 8
        for (int i = tid; i < SMEM_U_FLOATS / 4; i += 128) dst[i] = src[i];
    }
    __syncthreads();

    // hoisted per-thread constants
    const int a_b = tid >> 6;          // A staging: row parity
    const int a_k = tid & 63;          //            k within chunk
    float* hbuf0 = g_h[dir][0];
    float* hbuf1 = g_h[dir][1];

    // recurrent biases for this thread's units (constant over t)
    const int u0 = j0 + tg * 2;        // ut=0 unit base
    const int u1 = j0 + 8 + tg * 2;    // ut=1 unit base
    float2 brz0 = *(const float2*)(brec + u0);
    float2 brr0 = *(const float2*)(brec + UNITS + u0);
    float2 brh0 = *(const float2*)(brec + 2 * UNITS + u0);
    float2 brz1 = *(const float2*)(brec + u1);
    float2 brr1 = *(const float2*)(brec + UNITS + u1);
    float2 brh1 = *(const float2*)(brec + 2 * UNITS + u1);

    const float2* Bw = ((const float2*)Up) + lane;   // fragment stream base

    for (int t = 0; t < SEQ; t++) {
        // ---- acquire: wait for all 64 CTAs of this dir to finish step t-1 ----
        if (t > 0) {
            if (tid == 0) {
                while (((volatile int*)g_cnt)[dir] < t * 64) { }
                __threadfence();
            }
            __syncthreads();
        }

        const int parity = t & 1;
        const float* h_in  = parity ? hbuf1 : hbuf0;
        float*       h_out = parity ? hbuf0 : hbuf1;
        const int t_tok = dir ? (SEQ - 1 - t) : t;
        const float* gx = &g_gx[dir][(size_t)t * (BATCH * N3)];

        // masks for this thread's two rows
        const bool m0 = (x[(bb + g    ) * SEQ + t_tok] != 0);
        const bool m1 = (x[(bb + g + 8) * SEQ + t_tok] != 0);

        float c[6][4];
        #pragma unroll
        for (int i = 0; i < 6; i++)
            #pragma unroll
            for (int e = 0; e < 4; e++) c[i][e] = 0.0f;

        // prefetch A chunk 0
        float a_reg[32];
        #pragma unroll
        for (int i = 0; i < 32; i++)
            a_reg[i] = h_in[(2 * i + a_b) * UNITS + a_k];

        for (int kk = 0; kk < 16; kk++) {
            #pragma unroll
            for (int i = 0; i < 32; i++) As[2 * i + a_b][a_k] = tf32r(a_reg[i]);
            __syncthreads();

            if (kk < 15) {
                const int k0 = (kk + 1) * 64;
                #pragma unroll
                for (int i = 0; i < 32; i++)
                    a_reg[i] = h_in[(2 * i + a_b) * UNITS + k0 + a_k];
            }

            #pragma unroll
            for (int ks = 0; ks < 8; ks++) {
                unsigned a0 = __float_as_uint(As[bb + g    ][ks * 8 + tg    ]);
                unsigned a1 = __float_as_uint(As[bb + g + 8][ks * 8 + tg    ]);
                unsigned a2 = __float_as_uint(As[bb + g    ][ks * 8 + tg + 4]);
                unsigned a3 = __float_as_uint(As[bb + g + 8][ks * 8 + tg + 4]);
                const float2* bp = Bw + (size_t)((kk * 8 + ks) * 6) * 32;
                #pragma unroll
                for (int nt = 0; nt < 6; nt++) {
                    float2 b = bp[nt * 32];
                    mma_tf32(c[nt][0], c[nt][1], c[nt][2], c[nt][3],
                             a0, a1, a2, a3,
                             __float_as_uint(b.x), __float_as_uint(b.y));
                }
            }
            __syncthreads();
        }

        // ---- fused GRU gate epilogue ----
        #pragma unroll
        for (int ut = 0; ut < 2; ut++) {
            const int u = ut ? u1 : u0;
            float2 brz = ut ? brz1 : brz0;
            float2 brr = ut ? brr1 : brr0;
            float2 brh = ut ? brh1 : brh0;
            #pragma unroll
            for (int rr = 0; rr < 2; rr++) {
                const int b = bb + g + rr * 8;
                const bool m = rr ? m1 : m0;
                const float* gxr = gx + (size_t)b * N3;
                float2 xz = *(const float2*)(gxr + u);
                float2 xr = *(const float2*)(gxr + UNITS + u);
                float2 xh = *(const float2*)(gxr + 2 * UNITS + u);
                float2 ho = *(const float2*)(h_in + b * UNITS + u);

                float hn[2];
                #pragma unroll
                for (int cc = 0; cc < 2; cc++) {
                    float cz = c[0 + ut][rr * 2 + cc];
                    float cr = c[2 + ut][rr * 2 + cc];
                    float ch = c[4 + ut][rr * 2 + cc];
                    float xzv = cc ? xz.y : xz.x;
                    float xrv = cc ? xr.y : xr.x;
                    float xhv = cc ? xh.y : xh.x;
                    float bz  = cc ? brz.y : brz.x;
                    float br  = cc ? brr.y : brr.x;
                    float bh  = cc ? brh.y : brh.x;
                    float hov = cc ? ho.y : ho.x;

                    float z  = sigmoidf_(xzv + cz + bz);
                    float r  = sigmoidf_(xrv + cr + br);
                    float hh = tanhf(xhv + r * (ch + bh));
                    float v  = z * hov + (1.0f - z) * hh;
                    hn[cc] = m ? v : hov;
                }
                *(float2*)(h_out + b * UNITS + u) = make_float2(hn[0], hn[1]);
                *(float2*)(out + (size_t)b * (SEQ * 2 * UNITS)
                               + (size_t)t_tok * (2 * UNITS)
                               + dir * UNITS + u) = make_float2(hn[0], hn[1]);
            }
        }

        // ---- release: publish h_out, signal arrival ----
        __threadfence();
        __syncthreads();
        if (tid == 0) atomicAdd(&g_cnt[dir], 1);
    }
}

// ---------------------------------------------------------------------------
// projection: state = tanh([hf, hb] @ Wp + bp)   [64,2048]@[2048,1024]
// ---------------------------------------------------------------------------
__global__ __launch_bounds__(256) void proj_kernel(
    const float* __restrict__ Wp, const float* __restrict__ bp,
    float* __restrict__ out_state)
{
    const int j  = blockIdx.x * 16 + (threadIdx.x & 15);
    const int b0 = (threadIdx.x >> 4) * 4;
    const float* hf = g_h[0][0];
    const float* hb = g_h[1][0];

    float acc[4] = {0.f, 0.f, 0.f, 0.f};
    #pragma unroll 4
    for (int k = 0; k < UNITS; k++) {
        float w = Wp[k * UNITS + j];
        #pragma unroll
        for (int i = 0; i < 4; i++) acc[i] += hf[(b0 + i) * UNITS + k] * w;
    }
    #pragma unroll 4
    for (int k = 0; k < UNITS; k++) {
        float w = Wp[(UNITS + k) * UNITS + j];
        #pragma unroll
        for (int i = 0; i < 4; i++) acc[i] += hb[(b0 + i) * UNITS + k] * w;
    }
    float bj = bp[j];
    #pragma unroll
    for (int i = 0; i < 4; i++)
        out_state[(b0 + i) * UNITS + j] = tanhf(acc[i] + bj);
}

// ---------------------------------------------------------------------------
// launcher
// ---------------------------------------------------------------------------
extern "C" void kernel_launch(void* const* d_in, const int* in_sizes, int n_in,
                              void* d_out, int out_size)
{
    const int*   x      = (const int*)  d_in[0];
    const float* hidden = (const float*)d_in[1];
    const float* emb    = (const float*)d_in[2];
    const float* Wf     = (const float*)d_in[3];
    const float* Uf     = (const float*)d_in[4];
    const float* bf_in  = (const float*)d_in[5];
    const float* bf_rec = (const float*)d_in[6];
    const float* Wb     = (const float*)d_in[7];
    const float* Ub     = (const float*)d_in[8];
    const float* bb_in  = (const float*)d_in[9];
    const float* bb_rec = (const float*)d_in[10];
    const float* Wp     = (const float*)d_in[11];
    const float* bp     = (const float*)d_in[12];
    float* out = (float*)d_out;

    (void)in_sizes; (void)n_in; (void)out_size;

    cudaFuncSetAttribute(recur_kernel,
                         cudaFuncAttributeMaxDynamicSharedMemorySize,
                         SMEM_TOTAL_B);

    init_h<<<(BATCH * UNITS + 255) / 256, 256>>>(hidden);

    pack_U<<<dim3(128, 64, 2), 384>>>(Uf, Ub);

    gx_kernel<<<dim3(SEQ, N3 / 64, 2), 128>>>(x, emb, Wf, bf_in, Wb, bb_in);

    recur_kernel<<<128, 128, SMEM_TOTAL_B>>>(x, bf_rec, bb_rec, out);

    proj_kernel<<<UNITS / 16, 256>>>(Wp, bp,
                                     out + (size_t)BATCH * SEQ * 2 * UNITS);
}